// round 1
// baseline (speedup 1.0000x reference)
#include <cuda_runtime.h>
#include <cuda_bf16.h>
#include <math.h>

#define NTOK 16384
#define HID  1024
#define FFN  4096
#define NE   8
#define NROWS (NTOK * 2)

// ---------------- device scratch (no allocations allowed) ----------------
__device__ int   g_cnt[NE];
__device__ int   g_cur[NE];
__device__ int   g_off[NE + 1];
__device__ int   g_topk_e[NROWS];
__device__ float g_topk_w[NROWS];
__device__ int   g_rowtok[NROWS];     // packed row -> token id
__device__ int   g_prow[NROWS];       // (token,k) -> packed row
__device__ float g_h[(size_t)NROWS * FFN];   // 512 MB
__device__ float g_y[(size_t)NROWS * HID];   // 128 MB

// ---------------- gating: warp per token ----------------
__global__ __launch_bounds__(256) void zero_kernel() {
    int t = threadIdx.x;
    if (t < NE) { g_cnt[t] = 0; g_cur[t] = 0; }
}

__global__ __launch_bounds__(256) void gate_kernel(const float* __restrict__ x,
                                                   const float* __restrict__ Wg,
                                                   const float* __restrict__ bg) {
    int warp = (blockIdx.x * blockDim.x + threadIdx.x) >> 5;
    int lane = threadIdx.x & 31;
    if (warp >= NTOK) return;
    const float* xr = x + (size_t)warp * HID;
    float acc[NE];
    #pragma unroll
    for (int e = 0; e < NE; e++) acc[e] = 0.f;
    for (int i = lane; i < HID; i += 32) {
        float xi = xr[i];
        #pragma unroll
        for (int e = 0; e < NE; e++) acc[e] += xi * Wg[i * NE + e];
    }
    #pragma unroll
    for (int o = 16; o; o >>= 1) {
        #pragma unroll
        for (int e = 0; e < NE; e++) acc[e] += __shfl_xor_sync(0xFFFFFFFFu, acc[e], o);
    }
    if (lane == 0) {
        float s[NE];
        #pragma unroll
        for (int e = 0; e < NE; e++) s[e] = acc[e] + bg[e];
        // top-2, jax tie semantics: lowest index wins on ties (strict >)
        int i0 = 0;
        #pragma unroll
        for (int e = 1; e < NE; e++) if (s[e] > s[i0]) i0 = e;
        int i1 = -1;
        #pragma unroll
        for (int e = 0; e < NE; e++) {
            if (e == i0) continue;
            if (i1 < 0 || s[e] > s[i1]) i1 = e;
        }
        float m  = s[i0];
        float e1 = expf(s[i1] - m);     // exp(s0-m)=1
        float denom = 1.f + e1;
        float w0 = 1.f / denom, w1 = e1 / denom;
        g_topk_e[warp * 2]     = i0;  g_topk_w[warp * 2]     = w0;
        g_topk_e[warp * 2 + 1] = i1;  g_topk_w[warp * 2 + 1] = w1;
        atomicAdd(&g_cnt[i0], 1);
        atomicAdd(&g_cnt[i1], 1);
    }
}

__global__ void scan_kernel() {
    // single thread: tiny exclusive scan
    g_off[0] = 0;
    for (int e = 0; e < NE; e++) g_off[e + 1] = g_off[e] + g_cnt[e];
}

__global__ __launch_bounds__(256) void assign_kernel() {
    int t = blockIdx.x * blockDim.x + threadIdx.x;
    if (t >= NTOK) return;
    #pragma unroll
    for (int k = 0; k < 2; k++) {
        int e = g_topk_e[t * 2 + k];
        int slot = atomicAdd(&g_cur[e], 1);
        int p = g_off[e] + slot;
        g_rowtok[p] = t;
        g_prow[t * 2 + k] = p;
    }
}

// ---------------- tiled SGEMM (128x128x16, 256 thr, 8x8 microtile) ----------------
#define BM 128
#define BN 128
#define BK 16

// h[p, :] = relu(x[rowtok[p], :] @ W1_e + b1_e)
__global__ __launch_bounds__(256) void gemm1_kernel(const float* __restrict__ x,
                                                    const float* __restrict__ W1,
                                                    const float* __restrict__ b1) {
    int e   = blockIdx.z;
    int cnt = g_cnt[e];
    int m0  = blockIdx.y * BM;
    if (m0 >= cnt) return;
    int off = g_off[e];
    int n0  = blockIdx.x * BN;
    const float* B = W1 + (size_t)e * HID * FFN;
    const float* bias = b1 + (size_t)e * FFN;

    __shared__ float As[BK][BM];
    __shared__ float Bs[BK][BN];

    int t  = threadIdx.x;
    int am = t >> 1;                 // 0..127
    int ak = (t & 1) * 8;            // 0 / 8
    int arow = m0 + am; if (arow >= cnt) arow = cnt - 1;
    const float* xr = x + (size_t)g_rowtok[off + arow] * HID;
    int bk = t >> 4;                 // 0..15
    int bn = (t & 15) * 8;           // 0..120
    int tx = t & 15, ty = t >> 4;

    float acc[8][8];
    #pragma unroll
    for (int i = 0; i < 8; i++)
        #pragma unroll
        for (int j = 0; j < 8; j++) acc[i][j] = 0.f;

    for (int k0 = 0; k0 < HID; k0 += BK) {
        float4 a0 = *(const float4*)(xr + k0 + ak);
        float4 a1 = *(const float4*)(xr + k0 + ak + 4);
        const float* bp = B + (size_t)(k0 + bk) * FFN + n0 + bn;
        float4 b0 = *(const float4*)(bp);
        float4 b1v = *(const float4*)(bp + 4);
        __syncthreads();
        As[ak + 0][am] = a0.x; As[ak + 1][am] = a0.y;
        As[ak + 2][am] = a0.z; As[ak + 3][am] = a0.w;
        As[ak + 4][am] = a1.x; As[ak + 5][am] = a1.y;
        As[ak + 6][am] = a1.z; As[ak + 7][am] = a1.w;
        *(float4*)&Bs[bk][bn]     = b0;
        *(float4*)&Bs[bk][bn + 4] = b1v;
        __syncthreads();
        #pragma unroll
        for (int kk = 0; kk < BK; kk++) {
            float a[8], b[8];
            *(float4*)&a[0] = *(float4*)&As[kk][ty * 8];
            *(float4*)&a[4] = *(float4*)&As[kk][ty * 8 + 4];
            *(float4*)&b[0] = *(float4*)&Bs[kk][tx * 8];
            *(float4*)&b[4] = *(float4*)&Bs[kk][tx * 8 + 4];
            #pragma unroll
            for (int i = 0; i < 8; i++)
                #pragma unroll
                for (int j = 0; j < 8; j++) acc[i][j] += a[i] * b[j];
        }
    }
    // epilogue: +bias, relu
    #pragma unroll
    for (int i = 0; i < 8; i++) {
        int row = m0 + ty * 8 + i;
        if (row >= cnt) continue;
        float* hp = g_h + (size_t)(off + row) * FFN + n0 + tx * 8;
        #pragma unroll
        for (int j = 0; j < 8; j += 4) {
            float4 v;
            v.x = fmaxf(acc[i][j + 0] + bias[n0 + tx * 8 + j + 0], 0.f);
            v.y = fmaxf(acc[i][j + 1] + bias[n0 + tx * 8 + j + 1], 0.f);
            v.z = fmaxf(acc[i][j + 2] + bias[n0 + tx * 8 + j + 2], 0.f);
            v.w = fmaxf(acc[i][j + 3] + bias[n0 + tx * 8 + j + 3], 0.f);
            *(float4*)(hp + j) = v;
        }
    }
}

// y[p, :] = h[p, :] @ W2_e + b2_e
__global__ __launch_bounds__(256) void gemm2_kernel(const float* __restrict__ W2,
                                                    const float* __restrict__ b2) {
    int e   = blockIdx.z;
    int cnt = g_cnt[e];
    int m0  = blockIdx.y * BM;
    if (m0 >= cnt) return;
    int off = g_off[e];
    int n0  = blockIdx.x * BN;
    const float* B = W2 + (size_t)e * FFN * HID;
    const float* bias = b2 + (size_t)e * HID;

    __shared__ float As[BK][BM];
    __shared__ float Bs[BK][BN];

    int t  = threadIdx.x;
    int am = t >> 1;
    int ak = (t & 1) * 8;
    int arow = m0 + am; if (arow >= cnt) arow = cnt - 1;
    const float* hr = g_h + (size_t)(off + arow) * FFN;
    int bk = t >> 4;
    int bn = (t & 15) * 8;
    int tx = t & 15, ty = t >> 4;

    float acc[8][8];
    #pragma unroll
    for (int i = 0; i < 8; i++)
        #pragma unroll
        for (int j = 0; j < 8; j++) acc[i][j] = 0.f;

    for (int k0 = 0; k0 < FFN; k0 += BK) {
        float4 a0 = *(const float4*)(hr + k0 + ak);
        float4 a1 = *(const float4*)(hr + k0 + ak + 4);
        const float* bp = B + (size_t)(k0 + bk) * HID + n0 + bn;
        float4 b0 = *(const float4*)(bp);
        float4 b1v = *(const float4*)(bp + 4);
        __syncthreads();
        As[ak + 0][am] = a0.x; As[ak + 1][am] = a0.y;
        As[ak + 2][am] = a0.z; As[ak + 3][am] = a0.w;
        As[ak + 4][am] = a1.x; As[ak + 5][am] = a1.y;
        As[ak + 6][am] = a1.z; As[ak + 7][am] = a1.w;
        *(float4*)&Bs[bk][bn]     = b0;
        *(float4*)&Bs[bk][bn + 4] = b1v;
        __syncthreads();
        #pragma unroll
        for (int kk = 0; kk < BK; kk++) {
            float a[8], b[8];
            *(float4*)&a[0] = *(float4*)&As[kk][ty * 8];
            *(float4*)&a[4] = *(float4*)&As[kk][ty * 8 + 4];
            *(float4*)&b[0] = *(float4*)&Bs[kk][tx * 8];
            *(float4*)&b[4] = *(float4*)&Bs[kk][tx * 8 + 4];
            #pragma unroll
            for (int i = 0; i < 8; i++)
                #pragma unroll
                for (int j = 0; j < 8; j++) acc[i][j] += a[i] * b[j];
        }
    }
    #pragma unroll
    for (int i = 0; i < 8; i++) {
        int row = m0 + ty * 8 + i;
        if (row >= cnt) continue;
        float* yp = g_y + (size_t)(off + row) * HID + n0 + tx * 8;
        #pragma unroll
        for (int j = 0; j < 8; j += 4) {
            float4 v;
            v.x = acc[i][j + 0] + bias[n0 + tx * 8 + j + 0];
            v.y = acc[i][j + 1] + bias[n0 + tx * 8 + j + 1];
            v.z = acc[i][j + 2] + bias[n0 + tx * 8 + j + 2];
            v.w = acc[i][j + 3] + bias[n0 + tx * 8 + j + 3];
            *(float4*)(yp + j) = v;
        }
    }
}

// out[t] = w0 * y[p0] + w1 * y[p1]   (bit-deterministic; no atomics)
__global__ __launch_bounds__(256) void combine_kernel(float* __restrict__ out) {
    int i = blockIdx.x * blockDim.x + threadIdx.x;   // over NTOK * HID/4
    if (i >= NTOK * (HID / 4)) return;
    int tkn = i / (HID / 4);
    int c   = (i % (HID / 4)) * 4;
    int p0 = g_prow[tkn * 2], p1 = g_prow[tkn * 2 + 1];
    float w0 = g_topk_w[tkn * 2], w1 = g_topk_w[tkn * 2 + 1];
    float4 a = *(const float4*)(g_y + (size_t)p0 * HID + c);
    float4 b = *(const float4*)(g_y + (size_t)p1 * HID + c);
    float4 v;
    v.x = w0 * a.x + w1 * b.x;
    v.y = w0 * a.y + w1 * b.y;
    v.z = w0 * a.z + w1 * b.z;
    v.w = w0 * a.w + w1 * b.w;
    *(float4*)(out + (size_t)tkn * HID + c) = v;
}

// ---------------- launch ----------------
extern "C" void kernel_launch(void* const* d_in, const int* in_sizes, int n_in,
                              void* d_out, int out_size) {
    const float* x  = (const float*)d_in[0];
    const float* Wg = (const float*)d_in[1];
    const float* bg = (const float*)d_in[2];
    const float* W1 = (const float*)d_in[3];
    const float* b1 = (const float*)d_in[4];
    const float* W2 = (const float*)d_in[5];
    const float* b2 = (const float*)d_in[6];
    float* out = (float*)d_out;

    zero_kernel<<<1, 256>>>();
    gate_kernel<<<(NTOK * 32) / 256, 256>>>(x, Wg, bg);
    scan_kernel<<<1, 1>>>();
    assign_kernel<<<NTOK / 256, 256>>>();
    {
        dim3 grid(FFN / BN, NTOK / BM, NE);   // early-exit on cnt
        gemm1_kernel<<<grid, 256>>>(x, W1, b1);
    }
    {
        dim3 grid(HID / BN, NTOK / BM, NE);
        gemm2_kernel<<<grid, 256>>>(W2, b2);
    }
    combine_kernel<<<(NTOK * (HID / 4)) / 256, 256>>>(out);
}

// round 7
// speedup vs baseline: 2.4778x; 2.4778x over previous
#include <cuda_runtime.h>
#include <cuda_bf16.h>
#include <math.h>
#include <stdint.h>

#define NTOK 16384
#define HID  1024
#define FFN  4096
#define NE   8
#define NROWS (NTOK * 2)
#define NROWSP (NROWS + NE * 128)     // padded rows upper bound = 33792
#define MAXTILES (NROWSP / 128)       // 264

// ---------------- device scratch ----------------
__device__ int   g_cnt[NE];
__device__ int   g_cur[NE];
__device__ int   g_po[NE + 1];
__device__ int   g_ntiles;
__device__ int   g_bad1;
__device__ int   g_bad2;
__device__ int   g_tile_e[MAXTILES];
__device__ int   g_topk_e[NROWS];
__device__ float g_topk_w[NROWS];
__device__ int   g_rowtok[NROWSP];
__device__ int   g_prow[NROWS];
__device__ float g_xg[(size_t)NROWSP * HID];
__device__ float g_h[(size_t)NROWSP * FFN];
__device__ float g_y[(size_t)NROWSP * HID];
__device__ float g_w1t[(size_t)NE * FFN * HID];   // [e][n(ffn)][k(hid)]
__device__ float g_w2t[(size_t)NE * HID * FFN];   // [e][n(hid)][k(ffn)]

// ---------------- helpers ----------------
__device__ __forceinline__ float rn_tf32(float v) {
    float o;
    asm("cvt.rna.tf32.f32 %0, %1;" : "=f"(o) : "f"(v));
    return o;
}

__device__ __forceinline__ void mma_tf32(float& c0, float& c1, float& c2, float& c3,
                                         uint32_t a0, uint32_t a1, uint32_t a2, uint32_t a3,
                                         uint32_t b0, uint32_t b1) {
    asm volatile(
        "mma.sync.aligned.m16n8k8.row.col.f32.tf32.tf32.f32 "
        "{%0,%1,%2,%3}, {%4,%5,%6,%7}, {%8,%9}, {%0,%1,%2,%3};"
        : "+f"(c0), "+f"(c1), "+f"(c2), "+f"(c3)
        : "r"(a0), "r"(a1), "r"(a2), "r"(a3), "r"(b0), "r"(b1));
}

// ---------------- gating ----------------
__global__ __launch_bounds__(256) void zero_kernel() {
    int t = threadIdx.x;
    if (t < NE) { g_cnt[t] = 0; g_cur[t] = 0; }
    if (t == 8) g_bad1 = 0;
    if (t == 9) g_bad2 = 0;
}

__global__ __launch_bounds__(256) void gate_kernel(const float* __restrict__ x,
                                                   const float* __restrict__ Wg,
                                                   const float* __restrict__ bg) {
    int warp = (blockIdx.x * blockDim.x + threadIdx.x) >> 5;
    int lane = threadIdx.x & 31;
    if (warp >= NTOK) return;
    const float* xr = x + (size_t)warp * HID;
    float acc[NE];
    #pragma unroll
    for (int e = 0; e < NE; e++) acc[e] = 0.f;
    for (int i = lane; i < HID; i += 32) {
        float xi = xr[i];
        #pragma unroll
        for (int e = 0; e < NE; e++) acc[e] += xi * Wg[i * NE + e];
    }
    #pragma unroll
    for (int o = 16; o; o >>= 1) {
        #pragma unroll
        for (int e = 0; e < NE; e++) acc[e] += __shfl_xor_sync(0xFFFFFFFFu, acc[e], o);
    }
    if (lane == 0) {
        float s[NE];
        #pragma unroll
        for (int e = 0; e < NE; e++) s[e] = acc[e] + bg[e];
        int i0 = 0;
        #pragma unroll
        for (int e = 1; e < NE; e++) if (s[e] > s[i0]) i0 = e;
        int i1 = -1;
        #pragma unroll
        for (int e = 0; e < NE; e++) {
            if (e == i0) continue;
            if (i1 < 0 || s[e] > s[i1]) i1 = e;
        }
        float e1 = expf(s[i1] - s[i0]);
        float denom = 1.f + e1;
        g_topk_e[warp * 2]     = i0;  g_topk_w[warp * 2]     = 1.f / denom;
        g_topk_e[warp * 2 + 1] = i1;  g_topk_w[warp * 2 + 1] = e1 / denom;
        atomicAdd(&g_cnt[i0], 1);
        atomicAdd(&g_cnt[i1], 1);
    }
}

__global__ void scan_kernel() {
    int acc = 0, t = 0;
    for (int e = 0; e < NE; e++) {
        g_po[e] = acc;
        int nt = (g_cnt[e] + 127) >> 7;
        for (int i = 0; i < nt; i++) g_tile_e[t++] = e;
        acc += nt << 7;
    }
    g_po[NE] = acc;
    g_ntiles = t;
}

__global__ __launch_bounds__(256) void assign_kernel() {
    int t = blockIdx.x * blockDim.x + threadIdx.x;
    if (t >= NTOK) return;
    #pragma unroll
    for (int k = 0; k < 2; k++) {
        int e = g_topk_e[t * 2 + k];
        int p = g_po[e] + atomicAdd(&g_cur[e], 1);
        g_rowtok[p] = t;
        g_prow[t * 2 + k] = p;
    }
}

__global__ __launch_bounds__(256) void padfill_kernel() {
    int r = blockIdx.x * 256 + threadIdx.x;
    if (r >= g_po[NE]) return;
    int e = 0;
    while (r >= g_po[e + 1]) e++;
    if (r - g_po[e] >= g_cnt[e]) g_rowtok[r] = 0;
}

// gather x rows (RN-rounded to tf32) into padded g_xg
__global__ __launch_bounds__(256) void gather_kernel(const float* __restrict__ x) {
    int row = blockIdx.x;
    if (row >= g_po[NE]) return;
    int tok = g_rowtok[row];
    const float4* s = (const float4*)(x + (size_t)tok * HID);
    float4* d = (float4*)(g_xg + (size_t)row * HID);
    float4 v = s[threadIdx.x];
    v.x = rn_tf32(v.x); v.y = rn_tf32(v.y); v.z = rn_tf32(v.z); v.w = rn_tf32(v.w);
    d[threadIdx.x] = v;
}

// transpose src[e][r][c] (RxC) -> g_w1t/g_w2t[e][c][r], RN-rounded to tf32.
// NOTE: destination selected in DEVICE code — __device__ symbols must never be
// passed as host-side kernel arguments (host shadow address, silent garbage).
template<bool TOW1>
__global__ __launch_bounds__(256) void transpose_kernel(const float* __restrict__ src) {
    constexpr int R = TOW1 ? HID : FFN;
    constexpr int C = TOW1 ? FFN : HID;
    float* __restrict__ dstbase = TOW1 ? g_w1t : g_w2t;
    __shared__ float t[32][33];
    int e = blockIdx.z;
    int c0 = blockIdx.x * 32, r0 = blockIdx.y * 32;
    const float* s = src + (size_t)e * R * C;
    float* d = dstbase + (size_t)e * R * C;
    int tx = threadIdx.x & 31, ty = threadIdx.x >> 5;
    #pragma unroll
    for (int i = 0; i < 32; i += 8)
        t[ty + i][tx] = rn_tf32(s[(size_t)(r0 + ty + i) * C + c0 + tx]);
    __syncthreads();
    #pragma unroll
    for (int i = 0; i < 32; i += 8)
        d[(size_t)(c0 + ty + i) * R + r0 + tx] = t[tx][ty + i];
}

// ---------------- tf32 mma GEMM: 128x128x32, synchronous double buffer ----------------
#define BK 32
#define KSTR 36
#define TILEF (128 * KSTR)            // 4608 floats
#define STGF (2 * TILEF)              // 9216 floats per stage (A+B)
#define MM_SMEM (2 * STGF * 4)        // 73728 bytes

__device__ __forceinline__ void ld_chunk(const float* __restrict__ Ab,
                                         const float* __restrict__ Bb,
                                         int KD, int t, int k0,
                                         float4* ra, float4* rb) {
    #pragma unroll
    for (int j = 0; j < 4; j++) {
        int u = t + 256 * j;
        int r = u >> 3, c = u & 7;
        ra[j] = *(const float4*)(Ab + (size_t)r * KD + c * 4 + k0);
        rb[j] = *(const float4*)(Bb + (size_t)r * KD + c * 4 + k0);
    }
}

__device__ __forceinline__ void st_chunk(float* smbase, int t,
                                         const float4* ra, const float4* rb) {
    #pragma unroll
    for (int j = 0; j < 4; j++) {
        int u = t + 256 * j;
        int r = u >> 3, c = u & 7;
        *(float4*)(smbase + r * KSTR + c * 4) = ra[j];
        *(float4*)(smbase + TILEF + r * KSTR + c * 4) = rb[j];
    }
}

template<int KD, int ND, bool FIRST>
__global__ __launch_bounds__(256, 1) void mma_gemm(const float* __restrict__ bias_all) {
    int tile = blockIdx.y;
    if (tile >= g_ntiles) return;
    const float* Amat = FIRST ? g_xg  : g_h;
    const float* Bmat = FIRST ? g_w1t : g_w2t;
    float*       Omat = FIRST ? g_h   : g_y;
    int e  = g_tile_e[tile];
    int n0 = blockIdx.x * 128;
    size_t m0 = (size_t)tile * 128;
    const float* Ab = Amat + m0 * KD;
    const float* Bb = Bmat + ((size_t)e * ND + n0) * KD;
    const float* biasb = bias_all + (size_t)e * ND + n0;

    extern __shared__ float sm[];
    int t = threadIdx.x;
    int wid = t >> 5, lane = t & 31;
    int wm = wid & 1, wn = wid >> 1;       // warp tile: rows wm*64, cols wn*32
    int qr = lane >> 2, qc = lane & 3;

    constexpr int NK = KD / BK;

    float4 ra[4], rb[4];
    ld_chunk(Ab, Bb, KD, t, 0, ra, rb);
    st_chunk(sm, t, ra, rb);
    __syncthreads();

    float acc[4][4][4];
    #pragma unroll
    for (int mi = 0; mi < 4; mi++)
        #pragma unroll
        for (int ni = 0; ni < 4; ni++)
            #pragma unroll
            for (int r = 0; r < 4; r++) acc[mi][ni][r] = 0.f;

    for (int i = 0; i < NK; i++) {
        if (i + 1 < NK) ld_chunk(Ab, Bb, KD, t, (i + 1) * BK, ra, rb);
        const uint32_t* As = (const uint32_t*)(sm + (i & 1) * STGF);
        const uint32_t* Bs = As + TILEF;
        #pragma unroll
        for (int kk = 0; kk < 4; kk++) {
            int k = kk * 8;
            uint32_t a[4][4];
            #pragma unroll
            for (int mi = 0; mi < 4; mi++) {
                int rbse = wm * 64 + mi * 16;
                a[mi][0] = As[(rbse + qr) * KSTR + k + qc];
                a[mi][1] = As[(rbse + 8 + qr) * KSTR + k + qc];
                a[mi][2] = As[(rbse + qr) * KSTR + k + 4 + qc];
                a[mi][3] = As[(rbse + 8 + qr) * KSTR + k + 4 + qc];
            }
            uint32_t b[4][2];
            #pragma unroll
            for (int ni = 0; ni < 4; ni++) {
                int nb = wn * 32 + ni * 8;
                b[ni][0] = Bs[(nb + qr) * KSTR + k + qc];
                b[ni][1] = Bs[(nb + qr) * KSTR + k + 4 + qc];
            }
            #pragma unroll
            for (int mi = 0; mi < 4; mi++)
                #pragma unroll
                for (int ni = 0; ni < 4; ni++)
                    mma_tf32(acc[mi][ni][0], acc[mi][ni][1], acc[mi][ni][2], acc[mi][ni][3],
                             a[mi][0], a[mi][1], a[mi][2], a[mi][3],
                             b[ni][0], b[ni][1]);
        }
        if (i + 1 < NK) st_chunk(sm + ((i + 1) & 1) * STGF, t, ra, rb);
        __syncthreads();
    }

    #pragma unroll
    for (int mi = 0; mi < 4; mi++) {
        int row0 = wm * 64 + mi * 16 + qr;
        float* o0 = Omat + (m0 + row0) * ND + n0;
        float* o1 = o0 + (size_t)8 * ND;
        #pragma unroll
        for (int ni = 0; ni < 4; ni++) {
            int col = wn * 32 + ni * 8 + qc * 2;
            float bx = biasb[col], by = biasb[col + 1];
            float2 v0, v1;
            v0.x = acc[mi][ni][0] + bx;  v0.y = acc[mi][ni][1] + by;
            v1.x = acc[mi][ni][2] + bx;  v1.y = acc[mi][ni][3] + by;
            if (FIRST) {
                v0.x = rn_tf32(fmaxf(v0.x, 0.f));  v0.y = rn_tf32(fmaxf(v0.y, 0.f));
                v1.x = rn_tf32(fmaxf(v1.x, 0.f));  v1.y = rn_tf32(fmaxf(v1.y, 0.f));
            }
            *(float2*)(o0 + col) = v0;
            *(float2*)(o1 + col) = v1;
        }
    }
}

// ---------------- sampled FFMA verification of the mma output ----------------
template<int KD, int ND, bool FIRST>
__global__ __launch_bounds__(256) void check_kernel(const float* __restrict__ bias_all) {
    int t = threadIdx.x;
    int nrows = g_po[NE];
    int r = (t & 15) * (nrows >> 4);
    if (r >= nrows) r = nrows - 1;
    int col = (t >> 4) * (ND / 16);
    int e = g_tile_e[r >> 7];
    const float* a = (FIRST ? g_xg : g_h) + (size_t)r * KD;
    const float* w = (FIRST ? g_w1t : g_w2t) + ((size_t)e * ND + col) * KD;
    float s = 0.f;
    for (int k = 0; k < KD; k++) s += a[k] * w[k];
    s += bias_all[(size_t)e * ND + col];
    if (FIRST) s = fmaxf(s, 0.f);
    float got = (FIRST ? g_h : g_y)[(size_t)r * ND + col];
    if (fabsf(got - s) > 0.02f * (fabsf(s) + 0.05f))
        atomicExch(FIRST ? &g_bad1 : &g_bad2, 1);
}

// ---------------- FFMA repair GEMM (R1-proven microkernel, K-major B) ----------------
template<int KD, int ND, bool FIRST>
__global__ __launch_bounds__(256) void repair_gemm(const float* __restrict__ bias_all) {
    int bad = FIRST ? g_bad1 : (g_bad1 | g_bad2);
    if (!bad) return;
    int tile = blockIdx.y;
    if (tile >= g_ntiles) return;
    const float* Amat = FIRST ? g_xg  : g_h;
    const float* Bmat = FIRST ? g_w1t : g_w2t;
    float*       Omat = FIRST ? g_h   : g_y;
    int e  = g_tile_e[tile];
    int n0 = blockIdx.x * 128;
    size_t m0 = (size_t)tile * 128;
    const float* Ab = Amat + m0 * KD;
    const float* Bt = Bmat + ((size_t)e * ND + n0) * KD;   // [n][k], 128 rows
    const float* biasb = bias_all + (size_t)e * ND + n0;

    __shared__ float As[16][128];
    __shared__ float Bs[16][128];

    int t = threadIdx.x;
    int rr = t >> 1;                 // 0..127 (row for both A and Bt)
    int kc = (t & 1) * 8;            // 0 / 8
    int tx = t & 15, ty = t >> 4;

    float acc[8][8];
    #pragma unroll
    for (int i = 0; i < 8; i++)
        #pragma unroll
        for (int j = 0; j < 8; j++) acc[i][j] = 0.f;

    for (int k0 = 0; k0 < KD; k0 += 16) {
        float4 a0 = *(const float4*)(Ab + (size_t)rr * KD + k0 + kc);
        float4 a1 = *(const float4*)(Ab + (size_t)rr * KD + k0 + kc + 4);
        float4 b0 = *(const float4*)(Bt + (size_t)rr * KD + k0 + kc);
        float4 b1 = *(const float4*)(Bt + (size_t)rr * KD + k0 + kc + 4);
        __syncthreads();
        As[kc + 0][rr] = a0.x; As[kc + 1][rr] = a0.y;
        As[kc + 2][rr] = a0.z; As[kc + 3][rr] = a0.w;
        As[kc + 4][rr] = a1.x; As[kc + 5][rr] = a1.y;
        As[kc + 6][rr] = a1.z; As[kc + 7][rr] = a1.w;
        Bs[kc + 0][rr] = b0.x; Bs[kc + 1][rr] = b0.y;
        Bs[kc + 2][rr] = b0.z; Bs[kc + 3][rr] = b0.w;
        Bs[kc + 4][rr] = b1.x; Bs[kc + 5][rr] = b1.y;
        Bs[kc + 6][rr] = b1.z; Bs[kc + 7][rr] = b1.w;
        __syncthreads();
        #pragma unroll
        for (int kk = 0; kk < 16; kk++) {
            float a[8], b[8];
            *(float4*)&a[0] = *(float4*)&As[kk][ty * 8];
            *(float4*)&a[4] = *(float4*)&As[kk][ty * 8 + 4];
            *(float4*)&b[0] = *(float4*)&Bs[kk][tx * 8];
            *(float4*)&b[4] = *(float4*)&Bs[kk][tx * 8 + 4];
            #pragma unroll
            for (int i = 0; i < 8; i++)
                #pragma unroll
                for (int j = 0; j < 8; j++) acc[i][j] += a[i] * b[j];
        }
    }
    #pragma unroll
    for (int i = 0; i < 8; i++) {
        float* op = Omat + (m0 + ty * 8 + i) * ND + n0 + tx * 8;
        #pragma unroll
        for (int j = 0; j < 8; j += 4) {
            float4 v;
            v.x = acc[i][j + 0] + biasb[tx * 8 + j + 0];
            v.y = acc[i][j + 1] + biasb[tx * 8 + j + 1];
            v.z = acc[i][j + 2] + biasb[tx * 8 + j + 2];
            v.w = acc[i][j + 3] + biasb[tx * 8 + j + 3];
            if (FIRST) {
                v.x = fmaxf(v.x, 0.f); v.y = fmaxf(v.y, 0.f);
                v.z = fmaxf(v.z, 0.f); v.w = fmaxf(v.w, 0.f);
            }
            *(float4*)(op + j) = v;
        }
    }
}

// ---------------- combine ----------------
__global__ __launch_bounds__(256) void combine_kernel(float* __restrict__ out) {
    int i = blockIdx.x * blockDim.x + threadIdx.x;
    if (i >= NTOK * (HID / 4)) return;
    int tkn = i / (HID / 4);
    int c   = (i % (HID / 4)) * 4;
    int p0 = g_prow[tkn * 2], p1 = g_prow[tkn * 2 + 1];
    float w0 = g_topk_w[tkn * 2], w1 = g_topk_w[tkn * 2 + 1];
    float4 a = *(const float4*)(g_y + (size_t)p0 * HID + c);
    float4 b = *(const float4*)(g_y + (size_t)p1 * HID + c);
    float4 v;
    v.x = w0 * a.x + w1 * b.x;
    v.y = w0 * a.y + w1 * b.y;
    v.z = w0 * a.z + w1 * b.z;
    v.w = w0 * a.w + w1 * b.w;
    *(float4*)(out + (size_t)tkn * HID + c) = v;
}

// ---------------- launch ----------------
extern "C" void kernel_launch(void* const* d_in, const int* in_sizes, int n_in,
                              void* d_out, int out_size) {
    const float* x  = (const float*)d_in[0];
    const float* Wg = (const float*)d_in[1];
    const float* bg = (const float*)d_in[2];
    const float* W1 = (const float*)d_in[3];
    const float* b1 = (const float*)d_in[4];
    const float* W2 = (const float*)d_in[5];
    const float* b2 = (const float*)d_in[6];
    float* out = (float*)d_out;

    cudaFuncSetAttribute(mma_gemm<HID, FFN, true>,
                         cudaFuncAttributeMaxDynamicSharedMemorySize, MM_SMEM);
    cudaFuncSetAttribute(mma_gemm<FFN, HID, false>,
                         cudaFuncAttributeMaxDynamicSharedMemorySize, MM_SMEM);

    zero_kernel<<<1, 256>>>();
    gate_kernel<<<(NTOK * 32) / 256, 256>>>(x, Wg, bg);
    scan_kernel<<<1, 1>>>();
    assign_kernel<<<NTOK / 256, 256>>>();
    padfill_kernel<<<NROWSP / 256, 256>>>();
    gather_kernel<<<NROWSP, 256>>>(x);
    transpose_kernel<true ><<<dim3(FFN / 32, HID / 32, NE), 256>>>(W1);
    transpose_kernel<false><<<dim3(HID / 32, FFN / 32, NE), 256>>>(W2);

    mma_gemm<HID, FFN, true><<<dim3(FFN / 128, MAXTILES), 256, MM_SMEM>>>(b1);
    check_kernel<HID, FFN, true><<<1, 256>>>(b1);
    repair_gemm<HID, FFN, true><<<dim3(FFN / 128, MAXTILES), 256>>>(b1);

    mma_gemm<FFN, HID, false><<<dim3(HID / 128, MAXTILES), 256, MM_SMEM>>>(b2);
    check_kernel<FFN, HID, false><<<1, 256>>>(b2);
    repair_gemm<FFN, HID, false><<<dim3(HID / 128, MAXTILES), 256>>>(b2);

    combine_kernel<<<(NTOK * (HID / 4)) / 256, 256>>>(out);
}

// round 8
// speedup vs baseline: 2.7389x; 1.1054x over previous
#include <cuda_runtime.h>
#include <cuda_bf16.h>
#include <math.h>
#include <stdint.h>

#define NTOK 16384
#define HID  1024
#define FFN  4096
#define NE   8
#define NROWS (NTOK * 2)
#define NROWSP (NROWS + NE * 128)     // padded rows upper bound = 33792
#define MAXTILES (NROWSP / 128)       // 264

// ---------------- device scratch ----------------
__device__ int   g_cnt[NE];
__device__ int   g_cur[NE];
__device__ int   g_po[NE + 1];
__device__ int   g_ntiles;
__device__ int   g_bad1;
__device__ int   g_bad2;
__device__ int   g_tile_e[MAXTILES];
__device__ int   g_topk_e[NROWS];
__device__ float g_topk_w[NROWS];
__device__ int   g_rowtok[NROWSP];
__device__ int   g_prow[NROWS];
__device__ float g_xg[(size_t)NROWSP * HID];
__device__ float g_h[(size_t)NROWSP * FFN];
__device__ float g_y[(size_t)NROWSP * HID];
__device__ float g_w1t[(size_t)NE * FFN * HID];   // [e][n(ffn)][k(hid)]
__device__ float g_w2t[(size_t)NE * HID * FFN];   // [e][n(hid)][k(ffn)]

// ---------------- helpers ----------------
__device__ __forceinline__ float rn_tf32(float v) {
    float o;
    asm("cvt.rna.tf32.f32 %0, %1;" : "=f"(o) : "f"(v));
    return o;
}

#define CP_ASYNC16(dst, src) \
    asm volatile("cp.async.cg.shared.global [%0], [%1], 16;" :: "r"(dst), "l"(src))
#define CP_COMMIT() asm volatile("cp.async.commit_group;" ::: "memory")
#define CP_WAIT(n)  asm volatile("cp.async.wait_group %0;" :: "n"(n) : "memory")

__device__ __forceinline__ void mma_tf32(float& c0, float& c1, float& c2, float& c3,
                                         uint32_t a0, uint32_t a1, uint32_t a2, uint32_t a3,
                                         uint32_t b0, uint32_t b1) {
    asm volatile(
        "mma.sync.aligned.m16n8k8.row.col.f32.tf32.tf32.f32 "
        "{%0,%1,%2,%3}, {%4,%5,%6,%7}, {%8,%9}, {%0,%1,%2,%3};"
        : "+f"(c0), "+f"(c1), "+f"(c2), "+f"(c3)
        : "r"(a0), "r"(a1), "r"(a2), "r"(a3), "r"(b0), "r"(b1));
}

// ---------------- gating ----------------
__global__ __launch_bounds__(256) void zero_kernel() {
    int t = threadIdx.x;
    if (t < NE) { g_cnt[t] = 0; g_cur[t] = 0; }
    if (t == 8) g_bad1 = 0;
    if (t == 9) g_bad2 = 0;
}

__global__ __launch_bounds__(256) void gate_kernel(const float* __restrict__ x,
                                                   const float* __restrict__ Wg,
                                                   const float* __restrict__ bg) {
    int warp = (blockIdx.x * blockDim.x + threadIdx.x) >> 5;
    int lane = threadIdx.x & 31;
    if (warp >= NTOK) return;
    const float* xr = x + (size_t)warp * HID;
    float acc[NE];
    #pragma unroll
    for (int e = 0; e < NE; e++) acc[e] = 0.f;
    for (int i = lane; i < HID; i += 32) {
        float xi = xr[i];
        #pragma unroll
        for (int e = 0; e < NE; e++) acc[e] += xi * Wg[i * NE + e];
    }
    #pragma unroll
    for (int o = 16; o; o >>= 1) {
        #pragma unroll
        for (int e = 0; e < NE; e++) acc[e] += __shfl_xor_sync(0xFFFFFFFFu, acc[e], o);
    }
    if (lane == 0) {
        float s[NE];
        #pragma unroll
        for (int e = 0; e < NE; e++) s[e] = acc[e] + bg[e];
        int i0 = 0;
        #pragma unroll
        for (int e = 1; e < NE; e++) if (s[e] > s[i0]) i0 = e;
        int i1 = -1;
        #pragma unroll
        for (int e = 0; e < NE; e++) {
            if (e == i0) continue;
            if (i1 < 0 || s[e] > s[i1]) i1 = e;
        }
        float e1 = expf(s[i1] - s[i0]);
        float denom = 1.f + e1;
        g_topk_e[warp * 2]     = i0;  g_topk_w[warp * 2]     = 1.f / denom;
        g_topk_e[warp * 2 + 1] = i1;  g_topk_w[warp * 2 + 1] = e1 / denom;
        atomicAdd(&g_cnt[i0], 1);
        atomicAdd(&g_cnt[i1], 1);
    }
}

__global__ void scan_kernel() {
    int acc = 0, t = 0;
    for (int e = 0; e < NE; e++) {
        g_po[e] = acc;
        int nt = (g_cnt[e] + 127) >> 7;
        for (int i = 0; i < nt; i++) g_tile_e[t++] = e;
        acc += nt << 7;
    }
    g_po[NE] = acc;
    g_ntiles = t;
}

__global__ __launch_bounds__(256) void assign_kernel() {
    int t = blockIdx.x * blockDim.x + threadIdx.x;
    if (t >= NTOK) return;
    #pragma unroll
    for (int k = 0; k < 2; k++) {
        int e = g_topk_e[t * 2 + k];
        int p = g_po[e] + atomicAdd(&g_cur[e], 1);
        g_rowtok[p] = t;
        g_prow[t * 2 + k] = p;
    }
}

__global__ __launch_bounds__(256) void padfill_kernel() {
    int r = blockIdx.x * 256 + threadIdx.x;
    if (r >= g_po[NE]) return;
    int e = 0;
    while (r >= g_po[e + 1]) e++;
    if (r - g_po[e] >= g_cnt[e]) g_rowtok[r] = 0;
}

// gather x rows (RN-rounded to tf32) into padded g_xg
__global__ __launch_bounds__(256) void gather_kernel(const float* __restrict__ x) {
    int row = blockIdx.x;
    if (row >= g_po[NE]) return;
    int tok = g_rowtok[row];
    const float4* s = (const float4*)(x + (size_t)tok * HID);
    float4* d = (float4*)(g_xg + (size_t)row * HID);
    float4 v = s[threadIdx.x];
    v.x = rn_tf32(v.x); v.y = rn_tf32(v.y); v.z = rn_tf32(v.z); v.w = rn_tf32(v.w);
    d[threadIdx.x] = v;
}

// transpose src[e][r][c] (RxC) -> g_w1t/g_w2t[e][c][r], RN-rounded to tf32.
// Destination selected in DEVICE code (never pass __device__ symbols as args).
template<bool TOW1>
__global__ __launch_bounds__(256) void transpose_kernel(const float* __restrict__ src) {
    constexpr int R = TOW1 ? HID : FFN;
    constexpr int C = TOW1 ? FFN : HID;
    float* __restrict__ dstbase = TOW1 ? g_w1t : g_w2t;
    __shared__ float t[32][33];
    int e = blockIdx.z;
    int c0 = blockIdx.x * 32, r0 = blockIdx.y * 32;
    const float* s = src + (size_t)e * R * C;
    float* d = dstbase + (size_t)e * R * C;
    int tx = threadIdx.x & 31, ty = threadIdx.x >> 5;
    #pragma unroll
    for (int i = 0; i < 32; i += 8)
        t[ty + i][tx] = rn_tf32(s[(size_t)(r0 + ty + i) * C + c0 + tx]);
    __syncthreads();
    #pragma unroll
    for (int i = 0; i < 32; i += 8)
        d[(size_t)(c0 + ty + i) * R + r0 + tx] = t[tx][ty + i];
}

// ---------------- tf32 mma GEMM: 128x256x32, 3-stage cp.async pipeline ----------------
#define BK 32
#define KSTR 36                    // smem row stride (floats): conflict-free fragments
#define A_FLOATS (128 * KSTR)      // 4608
#define B_FLOATS (256 * KSTR)      // 9216
#define STAGE_FLOATS (A_FLOATS + B_FLOATS)   // 13824
#define NSTG 3
#define MM_SMEM (NSTG * STAGE_FLOATS * 4)    // 165888 bytes

template<int KD, int ND, bool FIRST>
__global__ __launch_bounds__(256, 1) void mma_gemm(const float* __restrict__ bias_all) {
    int tile = blockIdx.y;
    if (tile >= g_ntiles) return;
    const float* Amat = FIRST ? g_xg  : g_h;
    const float* Bmat = FIRST ? g_w1t : g_w2t;
    float*       Omat = FIRST ? g_h   : g_y;
    int e  = g_tile_e[tile];
    int n0 = blockIdx.x * 256;
    size_t m0 = (size_t)tile * 128;
    const float* Ab = Amat + m0 * KD;
    const float* Bb = Bmat + ((size_t)e * ND + n0) * KD;
    const float* biasb = bias_all + (size_t)e * ND + n0;

    extern __shared__ float smem[];
    uint32_t smem_b = (uint32_t)__cvta_generic_to_shared(smem);

    int t = threadIdx.x;
    int wid = t >> 5, lane = t & 31;
    int wm = wid & 1, wn = wid >> 1;        // warp tile (wm*64, wn*64)
    int qr = lane >> 2, qc = lane & 3;

    // async-copy slots: A = 4 x 16B/thread, B = 8 x 16B/thread
    const float* srcA[4]; uint32_t dstA[4];
    #pragma unroll
    for (int j = 0; j < 4; j++) {
        int u = t + 256 * j;
        int m = u >> 3, c = u & 7;
        srcA[j] = Ab + (size_t)m * KD + c * 4;
        dstA[j] = smem_b + (uint32_t)(m * KSTR + c * 4) * 4;
    }
    const float* srcB[8]; uint32_t dstB[8];
    #pragma unroll
    for (int j = 0; j < 8; j++) {
        int u = t + 256 * j;
        int n = u >> 3, c = u & 7;
        srcB[j] = Bb + (size_t)n * KD + c * 4;
        dstB[j] = smem_b + (uint32_t)(A_FLOATS + n * KSTR + c * 4) * 4;
    }

    constexpr int NK = KD / BK;

    // prologue: stages 0,1
    #pragma unroll
    for (int p = 0; p < 2; p++) {
        uint32_t so = (uint32_t)p * (STAGE_FLOATS * 4);
        int k0 = p * BK;
        #pragma unroll
        for (int j = 0; j < 4; j++) CP_ASYNC16(dstA[j] + so, srcA[j] + k0);
        #pragma unroll
        for (int j = 0; j < 8; j++) CP_ASYNC16(dstB[j] + so, srcB[j] + k0);
        CP_COMMIT();
    }

    float acc[4][8][4];
    #pragma unroll
    for (int mi = 0; mi < 4; mi++)
        #pragma unroll
        for (int ni = 0; ni < 8; ni++)
            #pragma unroll
            for (int r = 0; r < 4; r++) acc[mi][ni][r] = 0.f;

    for (int i = 0; i < NK; i++) {
        if (i + 1 < NK) { CP_WAIT(1); } else { CP_WAIT(0); }
        __syncthreads();
        // prefetch stage i+2
        if (i + 2 < NK) {
            uint32_t so = (uint32_t)((i + 2) % NSTG) * (STAGE_FLOATS * 4);
            int k0 = (i + 2) * BK;
            #pragma unroll
            for (int j = 0; j < 4; j++) CP_ASYNC16(dstA[j] + so, srcA[j] + k0);
            #pragma unroll
            for (int j = 0; j < 8; j++) CP_ASYNC16(dstB[j] + so, srcB[j] + k0);
            CP_COMMIT();
        }
        // compute stage i
        const uint32_t* As = (const uint32_t*)(smem + (i % NSTG) * STAGE_FLOATS);
        const uint32_t* Bs = As + A_FLOATS;
        #pragma unroll
        for (int kk = 0; kk < 4; kk++) {
            int k = kk * 8;
            uint32_t a[4][4];
            #pragma unroll
            for (int mi = 0; mi < 4; mi++) {
                int rb = wm * 64 + mi * 16;
                a[mi][0] = As[(rb + qr) * KSTR + k + qc];
                a[mi][1] = As[(rb + 8 + qr) * KSTR + k + qc];
                a[mi][2] = As[(rb + qr) * KSTR + k + 4 + qc];
                a[mi][3] = As[(rb + 8 + qr) * KSTR + k + 4 + qc];
            }
            uint32_t b[8][2];
            #pragma unroll
            for (int ni = 0; ni < 8; ni++) {
                int nbr = wn * 64 + ni * 8;
                b[ni][0] = Bs[(nbr + qr) * KSTR + k + qc];
                b[ni][1] = Bs[(nbr + qr) * KSTR + k + 4 + qc];
            }
            #pragma unroll
            for (int mi = 0; mi < 4; mi++)
                #pragma unroll
                for (int ni = 0; ni < 8; ni++)
                    mma_tf32(acc[mi][ni][0], acc[mi][ni][1], acc[mi][ni][2], acc[mi][ni][3],
                             a[mi][0], a[mi][1], a[mi][2], a[mi][3],
                             b[ni][0], b[ni][1]);
        }
        __syncthreads();
    }

    // epilogue: bias (+relu +tf32-round for FIRST), direct global stores
    #pragma unroll
    for (int mi = 0; mi < 4; mi++) {
        int row0 = wm * 64 + mi * 16 + qr;
        float* o0 = Omat + (m0 + row0) * ND + n0;
        float* o1 = o0 + (size_t)8 * ND;
        #pragma unroll
        for (int ni = 0; ni < 8; ni++) {
            int col = wn * 64 + ni * 8 + qc * 2;
            float bx = biasb[col], by = biasb[col + 1];
            float2 v0, v1;
            v0.x = acc[mi][ni][0] + bx;  v0.y = acc[mi][ni][1] + by;
            v1.x = acc[mi][ni][2] + bx;  v1.y = acc[mi][ni][3] + by;
            if (FIRST) {
                v0.x = rn_tf32(fmaxf(v0.x, 0.f));  v0.y = rn_tf32(fmaxf(v0.y, 0.f));
                v1.x = rn_tf32(fmaxf(v1.x, 0.f));  v1.y = rn_tf32(fmaxf(v1.y, 0.f));
            }
            *(float2*)(o0 + col) = v0;
            *(float2*)(o1 + col) = v1;
        }
    }
}

// ---------------- sampled FFMA verification of the mma output ----------------
template<int KD, int ND, bool FIRST>
__global__ __launch_bounds__(256) void check_kernel(const float* __restrict__ bias_all) {
    int t = threadIdx.x;
    int nrows = g_po[NE];
    int r = (t & 15) * (nrows >> 4);
    if (r >= nrows) r = nrows - 1;
    int col = (t >> 4) * (ND / 16);
    int e = g_tile_e[r >> 7];
    const float* a = (FIRST ? g_xg : g_h) + (size_t)r * KD;
    const float* w = (FIRST ? g_w1t : g_w2t) + ((size_t)e * ND + col) * KD;
    float s = 0.f;
    for (int k = 0; k < KD; k++) s += a[k] * w[k];
    s += bias_all[(size_t)e * ND + col];
    if (FIRST) s = fmaxf(s, 0.f);
    float got = (FIRST ? g_h : g_y)[(size_t)r * ND + col];
    if (fabsf(got - s) > 0.02f * (fabsf(s) + 0.05f))
        atomicExch(FIRST ? &g_bad1 : &g_bad2, 1);
}

// ---------------- FFMA repair GEMM (safety net; runs only if check fails) ----------------
template<int KD, int ND, bool FIRST>
__global__ __launch_bounds__(256) void repair_gemm(const float* __restrict__ bias_all) {
    int bad = FIRST ? g_bad1 : (g_bad1 | g_bad2);
    if (!bad) return;
    int tile = blockIdx.y;
    if (tile >= g_ntiles) return;
    const float* Amat = FIRST ? g_xg  : g_h;
    const float* Bmat = FIRST ? g_w1t : g_w2t;
    float*       Omat = FIRST ? g_h   : g_y;
    int e  = g_tile_e[tile];
    int n0 = blockIdx.x * 128;
    size_t m0 = (size_t)tile * 128;
    const float* Ab = Amat + m0 * KD;
    const float* Bt = Bmat + ((size_t)e * ND + n0) * KD;
    const float* biasb = bias_all + (size_t)e * ND + n0;

    __shared__ float As[16][128];
    __shared__ float Bs[16][128];

    int t = threadIdx.x;
    int rr = t >> 1;
    int kc = (t & 1) * 8;
    int tx = t & 15, ty = t >> 4;

    float acc[8][8];
    #pragma unroll
    for (int i = 0; i < 8; i++)
        #pragma unroll
        for (int j = 0; j < 8; j++) acc[i][j] = 0.f;

    for (int k0 = 0; k0 < KD; k0 += 16) {
        float4 a0 = *(const float4*)(Ab + (size_t)rr * KD + k0 + kc);
        float4 a1 = *(const float4*)(Ab + (size_t)rr * KD + k0 + kc + 4);
        float4 b0 = *(const float4*)(Bt + (size_t)rr * KD + k0 + kc);
        float4 b1 = *(const float4*)(Bt + (size_t)rr * KD + k0 + kc + 4);
        __syncthreads();
        As[kc + 0][rr] = a0.x; As[kc + 1][rr] = a0.y;
        As[kc + 2][rr] = a0.z; As[kc + 3][rr] = a0.w;
        As[kc + 4][rr] = a1.x; As[kc + 5][rr] = a1.y;
        As[kc + 6][rr] = a1.z; As[kc + 7][rr] = a1.w;
        Bs[kc + 0][rr] = b0.x; Bs[kc + 1][rr] = b0.y;
        Bs[kc + 2][rr] = b0.z; Bs[kc + 3][rr] = b0.w;
        Bs[kc + 4][rr] = b1.x; Bs[kc + 5][rr] = b1.y;
        Bs[kc + 6][rr] = b1.z; Bs[kc + 7][rr] = b1.w;
        __syncthreads();
        #pragma unroll
        for (int kk = 0; kk < 16; kk++) {
            float a[8], b[8];
            *(float4*)&a[0] = *(float4*)&As[kk][ty * 8];
            *(float4*)&a[4] = *(float4*)&As[kk][ty * 8 + 4];
            *(float4*)&b[0] = *(float4*)&Bs[kk][tx * 8];
            *(float4*)&b[4] = *(float4*)&Bs[kk][tx * 8 + 4];
            #pragma unroll
            for (int i = 0; i < 8; i++)
                #pragma unroll
                for (int j = 0; j < 8; j++) acc[i][j] += a[i] * b[j];
        }
    }
    #pragma unroll
    for (int i = 0; i < 8; i++) {
        float* op = Omat + (m0 + ty * 8 + i) * ND + n0 + tx * 8;
        #pragma unroll
        for (int j = 0; j < 8; j += 4) {
            float4 v;
            v.x = acc[i][j + 0] + biasb[tx * 8 + j + 0];
            v.y = acc[i][j + 1] + biasb[tx * 8 + j + 1];
            v.z = acc[i][j + 2] + biasb[tx * 8 + j + 2];
            v.w = acc[i][j + 3] + biasb[tx * 8 + j + 3];
            if (FIRST) {
                v.x = fmaxf(v.x, 0.f); v.y = fmaxf(v.y, 0.f);
                v.z = fmaxf(v.z, 0.f); v.w = fmaxf(v.w, 0.f);
            }
            *(float4*)(op + j) = v;
        }
    }
}

// ---------------- combine ----------------
__global__ __launch_bounds__(256) void combine_kernel(float* __restrict__ out) {
    int i = blockIdx.x * blockDim.x + threadIdx.x;
    if (i >= NTOK * (HID / 4)) return;
    int tkn = i / (HID / 4);
    int c   = (i % (HID / 4)) * 4;
    int p0 = g_prow[tkn * 2], p1 = g_prow[tkn * 2 + 1];
    float w0 = g_topk_w[tkn * 2], w1 = g_topk_w[tkn * 2 + 1];
    float4 a = *(const float4*)(g_y + (size_t)p0 * HID + c);
    float4 b = *(const float4*)(g_y + (size_t)p1 * HID + c);
    float4 v;
    v.x = w0 * a.x + w1 * b.x;
    v.y = w0 * a.y + w1 * b.y;
    v.z = w0 * a.z + w1 * b.z;
    v.w = w0 * a.w + w1 * b.w;
    *(float4*)(out + (size_t)tkn * HID + c) = v;
}

// ---------------- launch ----------------
extern "C" void kernel_launch(void* const* d_in, const int* in_sizes, int n_in,
                              void* d_out, int out_size) {
    const float* x  = (const float*)d_in[0];
    const float* Wg = (const float*)d_in[1];
    const float* bg = (const float*)d_in[2];
    const float* W1 = (const float*)d_in[3];
    const float* b1 = (const float*)d_in[4];
    const float* W2 = (const float*)d_in[5];
    const float* b2 = (const float*)d_in[6];
    float* out = (float*)d_out;

    cudaFuncSetAttribute(mma_gemm<HID, FFN, true>,
                         cudaFuncAttributeMaxDynamicSharedMemorySize, MM_SMEM);
    cudaFuncSetAttribute(mma_gemm<FFN, HID, false>,
                         cudaFuncAttributeMaxDynamicSharedMemorySize, MM_SMEM);

    zero_kernel<<<1, 256>>>();
    gate_kernel<<<(NTOK * 32) / 256, 256>>>(x, Wg, bg);
    scan_kernel<<<1, 1>>>();
    assign_kernel<<<NTOK / 256, 256>>>();
    padfill_kernel<<<NROWSP / 256, 256>>>();
    gather_kernel<<<NROWSP, 256>>>(x);
    transpose_kernel<true ><<<dim3(FFN / 32, HID / 32, NE), 256>>>(W1);
    transpose_kernel<false><<<dim3(HID / 32, FFN / 32, NE), 256>>>(W2);

    mma_gemm<HID, FFN, true><<<dim3(FFN / 256, MAXTILES), 256, MM_SMEM>>>(b1);
    check_kernel<HID, FFN, true><<<1, 256>>>(b1);
    repair_gemm<HID, FFN, true><<<dim3(FFN / 128, MAXTILES), 256>>>(b1);

    mma_gemm<FFN, HID, false><<<dim3(HID / 256, MAXTILES), 256, MM_SMEM>>>(b2);
    check_kernel<FFN, HID, false><<<1, 256>>>(b2);
    repair_gemm<FFN, HID, false><<<dim3(HID / 128, MAXTILES), 256>>>(b2);

    combine_kernel<<<(NTOK * (HID / 4)) / 256, 256>>>(out);
}

// round 9
// speedup vs baseline: 2.8586x; 1.0437x over previous
#include <cuda_runtime.h>
#include <cuda_bf16.h>
#include <math.h>
#include <stdint.h>

#define NTOK 16384
#define HID  1024
#define FFN  4096
#define NE   8
#define NROWS (NTOK * 2)
#define NROWSP (NROWS + NE * 128)     // padded rows upper bound = 33792
#define MAXTILES (NROWSP / 128)       // 264

// ---------------- device scratch ----------------
__device__ int   g_cnt[NE];
__device__ int   g_cur[NE];
__device__ int   g_po[NE + 1];
__device__ int   g_ntiles;
__device__ int   g_bad1;
__device__ int   g_bad2;
__device__ int   g_tile_e[MAXTILES];
__device__ int   g_topk_e[NROWS];
__device__ float g_topk_w[NROWS];
__device__ int   g_rowtok[NROWSP];
__device__ int   g_prow[NROWS];
__device__ float g_xg[(size_t)NROWSP * HID];
__device__ float g_h[(size_t)NROWSP * FFN];
__device__ float g_y[(size_t)NROWSP * HID];

// ---------------- helpers ----------------
__device__ __forceinline__ float rn_tf32(float v) {
    float o;
    asm("cvt.rna.tf32.f32 %0, %1;" : "=f"(o) : "f"(v));
    return o;
}

#define CP_ASYNC16(dst, src) \
    asm volatile("cp.async.cg.shared.global [%0], [%1], 16;" :: "r"(dst), "l"(src))
#define CP_COMMIT() asm volatile("cp.async.commit_group;" ::: "memory")
#define CP_WAIT(n)  asm volatile("cp.async.wait_group %0;" :: "n"(n) : "memory")

__device__ __forceinline__ void mma_tf32(float& c0, float& c1, float& c2, float& c3,
                                         uint32_t a0, uint32_t a1, uint32_t a2, uint32_t a3,
                                         uint32_t b0, uint32_t b1) {
    asm volatile(
        "mma.sync.aligned.m16n8k8.row.col.f32.tf32.tf32.f32 "
        "{%0,%1,%2,%3}, {%4,%5,%6,%7}, {%8,%9}, {%0,%1,%2,%3};"
        : "+f"(c0), "+f"(c1), "+f"(c2), "+f"(c3)
        : "r"(a0), "r"(a1), "r"(a2), "r"(a3), "r"(b0), "r"(b1));
}

// ---------------- gating ----------------
__global__ __launch_bounds__(256) void zero_kernel() {
    int t = threadIdx.x;
    if (t < NE) { g_cnt[t] = 0; g_cur[t] = 0; }
    if (t == 8) g_bad1 = 0;
    if (t == 9) g_bad2 = 0;
}

__global__ __launch_bounds__(256) void gate_kernel(const float* __restrict__ x,
                                                   const float* __restrict__ Wg,
                                                   const float* __restrict__ bg) {
    int warp = (blockIdx.x * blockDim.x + threadIdx.x) >> 5;
    int lane = threadIdx.x & 31;
    if (warp >= NTOK) return;
    const float* xr = x + (size_t)warp * HID;
    float acc[NE];
    #pragma unroll
    for (int e = 0; e < NE; e++) acc[e] = 0.f;
    for (int i = lane; i < HID; i += 32) {
        float xi = xr[i];
        #pragma unroll
        for (int e = 0; e < NE; e++) acc[e] += xi * Wg[i * NE + e];
    }
    #pragma unroll
    for (int o = 16; o; o >>= 1) {
        #pragma unroll
        for (int e = 0; e < NE; e++) acc[e] += __shfl_xor_sync(0xFFFFFFFFu, acc[e], o);
    }
    if (lane == 0) {
        float s[NE];
        #pragma unroll
        for (int e = 0; e < NE; e++) s[e] = acc[e] + bg[e];
        int i0 = 0;
        #pragma unroll
        for (int e = 1; e < NE; e++) if (s[e] > s[i0]) i0 = e;
        int i1 = -1;
        #pragma unroll
        for (int e = 0; e < NE; e++) {
            if (e == i0) continue;
            if (i1 < 0 || s[e] > s[i1]) i1 = e;
        }
        float e1 = expf(s[i1] - s[i0]);
        float denom = 1.f + e1;
        g_topk_e[warp * 2]     = i0;  g_topk_w[warp * 2]     = 1.f / denom;
        g_topk_e[warp * 2 + 1] = i1;  g_topk_w[warp * 2 + 1] = e1 / denom;
        atomicAdd(&g_cnt[i0], 1);
        atomicAdd(&g_cnt[i1], 1);
    }
}

__global__ void scan_kernel() {
    int acc = 0, t = 0;
    for (int e = 0; e < NE; e++) {
        g_po[e] = acc;
        int nt = (g_cnt[e] + 127) >> 7;
        for (int i = 0; i < nt; i++) g_tile_e[t++] = e;
        acc += nt << 7;
    }
    g_po[NE] = acc;
    g_ntiles = t;
}

__global__ __launch_bounds__(256) void assign_kernel() {
    int t = blockIdx.x * blockDim.x + threadIdx.x;
    if (t >= NTOK) return;
    #pragma unroll
    for (int k = 0; k < 2; k++) {
        int e = g_topk_e[t * 2 + k];
        int p = g_po[e] + atomicAdd(&g_cur[e], 1);
        g_rowtok[p] = t;
        g_prow[t * 2 + k] = p;
    }
}

__global__ __launch_bounds__(256) void padfill_kernel() {
    int r = blockIdx.x * 256 + threadIdx.x;
    if (r >= g_po[NE]) return;
    int e = 0;
    while (r >= g_po[e + 1]) e++;
    if (r - g_po[e] >= g_cnt[e]) g_rowtok[r] = 0;
}

// gather x rows (RN-rounded to tf32) into padded g_xg
__global__ __launch_bounds__(256) void gather_kernel(const float* __restrict__ x) {
    int row = blockIdx.x;
    if (row >= g_po[NE]) return;
    int tok = g_rowtok[row];
    const float4* s = (const float4*)(x + (size_t)tok * HID);
    float4* d = (float4*)(g_xg + (size_t)row * HID);
    float4 v = s[threadIdx.x];
    v.x = rn_tf32(v.x); v.y = rn_tf32(v.y); v.z = rn_tf32(v.z); v.w = rn_tf32(v.w);
    d[threadIdx.x] = v;
}

// ---------------- tf32 mma GEMM: 128x256x32, 4-stage cp.async, single-sync loop ----------
// A smem: [128 m][36 k-stride], K-major rows.  B smem: [32 k][264 n-stride], native W rows.
#define BK 32
#define KSTR 36
#define BSTR 264
#define A_FLOATS (128 * KSTR)              // 4608
#define B_FLOATS (BK * BSTR)               // 8448
#define STAGE_FLOATS (A_FLOATS + B_FLOATS) // 13056
#define NSTG 4
#define MM_SMEM (NSTG * STAGE_FLOATS * 4)  // 208896 bytes

template<int KD, int ND, bool FIRST>
__global__ __launch_bounds__(256, 1) void mma_gemm(const float* __restrict__ W,
                                                   const float* __restrict__ bias_all) {
    int tile = blockIdx.y;
    if (tile >= g_ntiles) return;
    const float* Amat = FIRST ? g_xg : g_h;
    float*       Omat = FIRST ? g_h  : g_y;
    int e  = g_tile_e[tile];
    int n0 = blockIdx.x * 256;
    size_t m0 = (size_t)tile * 128;
    const float* Ab = Amat + m0 * KD;
    const float* Wb = W + (size_t)e * KD * ND + n0;     // [k][n] rows
    const float* biasb = bias_all + (size_t)e * ND + n0;

    extern __shared__ float smem[];
    uint32_t smem_b = (uint32_t)__cvta_generic_to_shared(smem);

    int t = threadIdx.x;
    int wid = t >> 5, lane = t & 31;
    int wm = wid & 1, wn = wid >> 1;        // warp tile (wm*64, wn*64)
    int qr = lane >> 2, qc = lane & 3;

    // async-copy slots: A = 4 x 16B/thread (m-row k-chunks), B = 8 x 16B/thread (k-row n-chunks)
    const float* srcA[4]; uint32_t dstA[4];
    #pragma unroll
    for (int j = 0; j < 4; j++) {
        int u = t + 256 * j;
        int m = u >> 3, c = u & 7;
        srcA[j] = Ab + (size_t)m * KD + c * 4;
        dstA[j] = smem_b + (uint32_t)(m * KSTR + c * 4) * 4;
    }
    const float* srcB[8]; uint32_t dstB[8];
    #pragma unroll
    for (int j = 0; j < 8; j++) {
        int u = t + 256 * j;
        int kk = u >> 6, c = u & 63;        // 64 chunks of 16B per 256-float k-row
        srcB[j] = Wb + (size_t)kk * ND + c * 4;
        dstB[j] = smem_b + (uint32_t)(A_FLOATS + kk * BSTR + c * 4) * 4;
    }

    constexpr int NK = KD / BK;

    // prologue: stages 0..2
    #pragma unroll
    for (int p = 0; p < NSTG - 1; p++) {
        uint32_t so = (uint32_t)p * (STAGE_FLOATS * 4);
        int k0 = p * BK;
        #pragma unroll
        for (int j = 0; j < 4; j++) CP_ASYNC16(dstA[j] + so, srcA[j] + k0);
        #pragma unroll
        for (int j = 0; j < 8; j++) CP_ASYNC16(dstB[j] + so, srcB[j] + (size_t)k0 * ND);
        CP_COMMIT();
    }

    float acc[4][8][4];
    #pragma unroll
    for (int mi = 0; mi < 4; mi++)
        #pragma unroll
        for (int ni = 0; ni < 8; ni++)
            #pragma unroll
            for (int r = 0; r < 4; r++) acc[mi][ni][r] = 0.f;

    for (int i = 0; i < NK; i++) {
        CP_WAIT(NSTG - 2);
        __syncthreads();
        // prefetch stage i+3 (always commit to keep the group ledger aligned)
        if (i + NSTG - 1 < NK) {
            uint32_t so = (uint32_t)((i + NSTG - 1) % NSTG) * (STAGE_FLOATS * 4);
            int k0 = (i + NSTG - 1) * BK;
            #pragma unroll
            for (int j = 0; j < 4; j++) CP_ASYNC16(dstA[j] + so, srcA[j] + k0);
            #pragma unroll
            for (int j = 0; j < 8; j++) CP_ASYNC16(dstB[j] + so, srcB[j] + (size_t)k0 * ND);
        }
        CP_COMMIT();
        // compute stage i
        const float* Asf = smem + (i % NSTG) * STAGE_FLOATS;
        const float* Bsf = Asf + A_FLOATS;
        const uint32_t* As = (const uint32_t*)Asf;
        #pragma unroll
        for (int kk = 0; kk < 4; kk++) {
            int k = kk * 8;
            uint32_t a[4][4];
            #pragma unroll
            for (int mi = 0; mi < 4; mi++) {
                int rb = wm * 64 + mi * 16;
                a[mi][0] = As[(rb + qr) * KSTR + k + qc];
                a[mi][1] = As[(rb + 8 + qr) * KSTR + k + qc];
                a[mi][2] = As[(rb + qr) * KSTR + k + 4 + qc];
                a[mi][3] = As[(rb + 8 + qr) * KSTR + k + 4 + qc];
            }
            uint32_t b[8][2];
            #pragma unroll
            for (int ni = 0; ni < 8; ni++) {
                int nbr = wn * 64 + ni * 8 + qr;
                b[ni][0] = __float_as_uint(rn_tf32(Bsf[(k + qc) * BSTR + nbr]));
                b[ni][1] = __float_as_uint(rn_tf32(Bsf[(k + 4 + qc) * BSTR + nbr]));
            }
            #pragma unroll
            for (int mi = 0; mi < 4; mi++)
                #pragma unroll
                for (int ni = 0; ni < 8; ni++)
                    mma_tf32(acc[mi][ni][0], acc[mi][ni][1], acc[mi][ni][2], acc[mi][ni][3],
                             a[mi][0], a[mi][1], a[mi][2], a[mi][3],
                             b[ni][0], b[ni][1]);
        }
    }

    __syncthreads();

    // epilogue: bias (+relu +tf32-round for FIRST), direct global stores
    #pragma unroll
    for (int mi = 0; mi < 4; mi++) {
        int row0 = wm * 64 + mi * 16 + qr;
        float* o0 = Omat + (m0 + row0) * ND + n0;
        float* o1 = o0 + (size_t)8 * ND;
        #pragma unroll
        for (int ni = 0; ni < 8; ni++) {
            int col = wn * 64 + ni * 8 + qc * 2;
            float bx = biasb[col], by = biasb[col + 1];
            float2 v0, v1;
            v0.x = acc[mi][ni][0] + bx;  v0.y = acc[mi][ni][1] + by;
            v1.x = acc[mi][ni][2] + bx;  v1.y = acc[mi][ni][3] + by;
            if (FIRST) {
                v0.x = rn_tf32(fmaxf(v0.x, 0.f));  v0.y = rn_tf32(fmaxf(v0.y, 0.f));
                v1.x = rn_tf32(fmaxf(v1.x, 0.f));  v1.y = rn_tf32(fmaxf(v1.y, 0.f));
            }
            *(float2*)(o0 + col) = v0;
            *(float2*)(o1 + col) = v1;
        }
    }
}

// ---------------- sampled FFMA verification of the mma output ----------------
template<int KD, int ND, bool FIRST>
__global__ __launch_bounds__(256) void check_kernel(const float* __restrict__ W,
                                                    const float* __restrict__ bias_all) {
    int t = threadIdx.x;
    int nrows = g_po[NE];
    int r = (t & 15) * (nrows >> 4);
    if (r >= nrows) r = nrows - 1;
    int col = (t >> 4) * (ND / 16);
    int e = g_tile_e[r >> 7];
    const float* a = (FIRST ? g_xg : g_h) + (size_t)r * KD;
    const float* w = W + (size_t)e * KD * ND + col;
    float s = 0.f;
    for (int k = 0; k < KD; k++) s += a[k] * rn_tf32(w[(size_t)k * ND]);
    s += bias_all[(size_t)e * ND + col];
    if (FIRST) s = fmaxf(s, 0.f);
    float got = (FIRST ? g_h : g_y)[(size_t)r * ND + col];
    if (fabsf(got - s) > 0.02f * (fabsf(s) + 0.05f))
        atomicExch(FIRST ? &g_bad1 : &g_bad2, 1);
}

// ---------------- FFMA repair GEMM (safety net; runs only if check fails) ----------------
template<int KD, int ND, bool FIRST>
__global__ __launch_bounds__(256) void repair_gemm(const float* __restrict__ W,
                                                   const float* __restrict__ bias_all) {
    int bad = FIRST ? g_bad1 : (g_bad1 | g_bad2);
    if (!bad) return;
    int tile = blockIdx.y;
    if (tile >= g_ntiles) return;
    const float* Amat = FIRST ? g_xg : g_h;
    float*       Omat = FIRST ? g_h  : g_y;
    int e  = g_tile_e[tile];
    int n0 = blockIdx.x * 128;
    size_t m0 = (size_t)tile * 128;
    const float* Ab = Amat + m0 * KD;
    const float* Bk = W + (size_t)e * KD * ND + n0;     // [k][n]
    const float* biasb = bias_all + (size_t)e * ND + n0;

    __shared__ float As[16][128];
    __shared__ float Bs[16][128];

    int t = threadIdx.x;
    int rr = t >> 1;
    int kc = (t & 1) * 8;
    int bk = t >> 4;                 // 0..15
    int bn = (t & 15) * 8;
    int tx = t & 15, ty = t >> 4;

    float acc[8][8];
    #pragma unroll
    for (int i = 0; i < 8; i++)
        #pragma unroll
        for (int j = 0; j < 8; j++) acc[i][j] = 0.f;

    for (int k0 = 0; k0 < KD; k0 += 16) {
        float4 a0 = *(const float4*)(Ab + (size_t)rr * KD + k0 + kc);
        float4 a1 = *(const float4*)(Ab + (size_t)rr * KD + k0 + kc + 4);
        const float* bp = Bk + (size_t)(k0 + bk) * ND + bn;
        float4 b0 = *(const float4*)(bp);
        float4 b1 = *(const float4*)(bp + 4);
        __syncthreads();
        As[kc + 0][rr] = a0.x; As[kc + 1][rr] = a0.y;
        As[kc + 2][rr] = a0.z; As[kc + 3][rr] = a0.w;
        As[kc + 4][rr] = a1.x; As[kc + 5][rr] = a1.y;
        As[kc + 6][rr] = a1.z; As[kc + 7][rr] = a1.w;
        *(float4*)&Bs[bk][bn]     = b0;
        *(float4*)&Bs[bk][bn + 4] = b1;
        __syncthreads();
        #pragma unroll
        for (int kk = 0; kk < 16; kk++) {
            float a[8], b[8];
            *(float4*)&a[0] = *(float4*)&As[kk][ty * 8];
            *(float4*)&a[4] = *(float4*)&As[kk][ty * 8 + 4];
            *(float4*)&b[0] = *(float4*)&Bs[kk][tx * 8];
            *(float4*)&b[4] = *(float4*)&Bs[kk][tx * 8 + 4];
            #pragma unroll
            for (int i = 0; i < 8; i++)
                #pragma unroll
                for (int j = 0; j < 8; j++) acc[i][j] += a[i] * b[j];
        }
    }
    #pragma unroll
    for (int i = 0; i < 8; i++) {
        float* op = Omat + (m0 + ty * 8 + i) * ND + n0 + tx * 8;
        #pragma unroll
        for (int j = 0; j < 8; j += 4) {
            float4 v;
            v.x = acc[i][j + 0] + biasb[tx * 8 + j + 0];
            v.y = acc[i][j + 1] + biasb[tx * 8 + j + 1];
            v.z = acc[i][j + 2] + biasb[tx * 8 + j + 2];
            v.w = acc[i][j + 3] + biasb[tx * 8 + j + 3];
            if (FIRST) {
                v.x = fmaxf(v.x, 0.f); v.y = fmaxf(v.y, 0.f);
                v.z = fmaxf(v.z, 0.f); v.w = fmaxf(v.w, 0.f);
            }
            *(float4*)(op + j) = v;
        }
    }
}

// ---------------- combine ----------------
__global__ __launch_bounds__(256) void combine_kernel(float* __restrict__ out) {
    int i = blockIdx.x * blockDim.x + threadIdx.x;
    if (i >= NTOK * (HID / 4)) return;
    int tkn = i / (HID / 4);
    int c   = (i % (HID / 4)) * 4;
    int p0 = g_prow[tkn * 2], p1 = g_prow[tkn * 2 + 1];
    float w0 = g_topk_w[tkn * 2], w1 = g_topk_w[tkn * 2 + 1];
    float4 a = *(const float4*)(g_y + (size_t)p0 * HID + c);
    float4 b = *(const float4*)(g_y + (size_t)p1 * HID + c);
    float4 v;
    v.x = w0 * a.x + w1 * b.x;
    v.y = w0 * a.y + w1 * b.y;
    v.z = w0 * a.z + w1 * b.z;
    v.w = w0 * a.w + w1 * b.w;
    *(float4*)(out + (size_t)tkn * HID + c) = v;
}

// ---------------- launch ----------------
extern "C" void kernel_launch(void* const* d_in, const int* in_sizes, int n_in,
                              void* d_out, int out_size) {
    const float* x  = (const float*)d_in[0];
    const float* Wg = (const float*)d_in[1];
    const float* bg = (const float*)d_in[2];
    const float* W1 = (const float*)d_in[3];
    const float* b1 = (const float*)d_in[4];
    const float* W2 = (const float*)d_in[5];
    const float* b2 = (const float*)d_in[6];
    float* out = (float*)d_out;

    cudaFuncSetAttribute(mma_gemm<HID, FFN, true>,
                         cudaFuncAttributeMaxDynamicSharedMemorySize, MM_SMEM);
    cudaFuncSetAttribute(mma_gemm<FFN, HID, false>,
                         cudaFuncAttributeMaxDynamicSharedMemorySize, MM_SMEM);

    zero_kernel<<<1, 256>>>();
    gate_kernel<<<(NTOK * 32) / 256, 256>>>(x, Wg, bg);
    scan_kernel<<<1, 1>>>();
    assign_kernel<<<NTOK / 256, 256>>>();
    padfill_kernel<<<NROWSP / 256, 256>>>();
    gather_kernel<<<NROWSP, 256>>>(x);

    mma_gemm<HID, FFN, true><<<dim3(FFN / 256, MAXTILES), 256, MM_SMEM>>>(W1, b1);
    check_kernel<HID, FFN, true><<<1, 256>>>(W1, b1);
    repair_gemm<HID, FFN, true><<<dim3(FFN / 128, MAXTILES), 256>>>(W1, b1);

    mma_gemm<FFN, HID, false><<<dim3(HID / 256, MAXTILES), 256, MM_SMEM>>>(W2, b2);
    check_kernel<FFN, HID, false><<<1, 256>>>(W2, b2);
    repair_gemm<FFN, HID, false><<<dim3(HID / 128, MAXTILES), 256>>>(W2, b2);

    combine_kernel<<<(NTOK * (HID / 4)) / 256, 256>>>(out);
}